// round 14
// baseline (speedup 1.0000x reference)
#include <cuda_runtime.h>
#include <cuda_fp16.h>
#include <cstdint>

#define D 128
#define GATES 512
#define NMAX 30016
#define MT 64
#define MG 32            // nodes per half-group in k_lstm
#define SROW 136
#define OROW 264
#define NBINS 64
#define NTHR 512

__device__ __half g_XWh[(size_t)NMAX * GATES];   // fp16 x-transform (bias folded)
__device__ __half g_Hh[(size_t)NMAX * D];
__device__ __half g_Wrec[GATES * D];
__device__ __half g_Wih [GATES * D];
__device__ __half g_Wout[D * 256];
__device__ float  g_bias[GATES];
__device__ int g_start[NMAX], g_deg[NMAX], g_perm[NMAX];
__device__ int g_hist[NBINS], g_offs[NBINS];
__device__ int g_tick[4];

__device__ __forceinline__ unsigned su(const void* p){ return (unsigned)__cvta_generic_to_shared(p); }
__device__ __forceinline__ void ldsm4(unsigned a,unsigned&r0,unsigned&r1,unsigned&r2,unsigned&r3){
  asm volatile("ldmatrix.sync.aligned.m8n8.x4.shared.b16 {%0,%1,%2,%3},[%4];"
    :"=r"(r0),"=r"(r1),"=r"(r2),"=r"(r3):"r"(a));
}
__device__ __forceinline__ void ldsm2(unsigned a,unsigned&r0,unsigned&r1){
  asm volatile("ldmatrix.sync.aligned.m8n8.x2.shared.b16 {%0,%1},[%2];"
    :"=r"(r0),"=r"(r1):"r"(a));
}
__device__ __forceinline__ void mmaf(float* d,const unsigned* a,unsigned b0,unsigned b1){
  asm volatile("mma.sync.aligned.m16n8k16.row.col.f32.f16.f16.f32 {%0,%1,%2,%3},{%4,%5,%6,%7},{%8,%9},{%0,%1,%2,%3};"
    :"+f"(d[0]),"+f"(d[1]),"+f"(d[2]),"+f"(d[3])
    :"r"(a[0]),"r"(a[1]),"r"(a[2]),"r"(a[3]),"r"(b0),"r"(b1));
}
__device__ __forceinline__ float ftanh(float x){ float y; asm("tanh.approx.f32 %0,%1;":"=f"(y):"f"(x)); return y; }
__device__ __forceinline__ float fsig (float x){ return fmaf(0.5f, ftanh(0.5f*x), 0.5f); }
__device__ __forceinline__ void barh(int id){ asm volatile("bar.sync %0, 256;" :: "r"(id) : "memory"); }

// ---------------- prep: reorder/convert weights (col' = unit*4 + gate) + clear counters ----------------
__global__ void k_prep(const float* Wih, const float* Whh, const float* bih,
                       const float* bhh, const float* Wout){
  int idx = blockIdx.x*blockDim.x + threadIdx.x;
  if (blockIdx.x == 0){
    if (threadIdx.x < NBINS) g_hist[threadIdx.x] = 0;
    if (threadIdx.x < 4) g_tick[threadIdx.x] = 0;
  }
  if (idx < GATES*D){
    int col = idx >> 7, k = idx & 127;
    int u = col >> 2, gg = col & 3;
    int j = gg*D + u;
    g_Wrec[col*D + k] = __float2half(Whh[j*D + k]);
    g_Wih [col*D + k] = __float2half(Wih[j*D + k]);
    if (k == 0) g_bias[col] = bih[j] + bhh[j];
  }
  if (idx < D*256){
    int j = idx >> 8, k = idx & 255;
    g_Wout[idx] = __float2half(Wout[k*D + j]);
  }
}

// ---------------- CSR from sorted src + degree clamp + fused histogram ----------------
__global__ void k_startdeg(const int* src, int E, int N, const int* pmax){
  __shared__ int h[NBINS];
  if (threadIdx.x < NBINS) h[threadIdx.x] = 0;
  __syncthreads();
  int i = blockIdx.x*blockDim.x + threadIdx.x;
  if (i < N){
    int md = pmax ? *pmax : 48;
    int lo=0, hi=E; while(lo<hi){int m=(lo+hi)>>1; if(src[m]<i) lo=m+1; else hi=m;}
    int s=lo; lo=s; hi=E; while(lo<hi){int m=(lo+hi)>>1; if(src[m]<i+1) lo=m+1; else hi=m;}
    g_start[i]=s; int d=lo-s; d = d<md ? d : md; g_deg[i]=d;
    atomicAdd(&h[min(d,NBINS-1)],1);
  }
  __syncthreads();
  if (threadIdx.x < NBINS && h[threadIdx.x]) atomicAdd(&g_hist[threadIdx.x], h[threadIdx.x]);
}
// offs[d] = count of nodes with bin > d  (descending-degree layout)
__global__ void k_scan(){
  __shared__ int s[NBINS];
  int d = threadIdx.x;
  s[d] = g_hist[d];
  __syncthreads();
  int run = 0;
  for (int j = d+1; j < NBINS; j++) run += s[j];
  g_offs[d] = run;
}
__global__ void k_scatter(int N){
  __shared__ int cnt[NBINS], base[NBINS];
  if(threadIdx.x<NBINS) cnt[threadIdx.x]=0;
  __syncthreads();
  int i=blockIdx.x*blockDim.x+threadIdx.x;
  int b=0,r=0;
  if(i<N){ b=min(g_deg[i],NBINS-1); r=atomicAdd(&cnt[b],1); }
  __syncthreads();
  if(threadIdx.x<NBINS && cnt[threadIdx.x]) base[threadIdx.x]=atomicAdd(&g_offs[threadIdx.x],cnt[threadIdx.x]);
  __syncthreads();
  if(i<N) g_perm[base[b]+r]=i;
}

// ---------------- XW = input @ W_ih'^T + bias'  (persistent, fp16 mma, fp16 store) ----------------
extern __shared__ __half smem[];
__global__ void __launch_bounds__(NTHR,1) k_xw(const float* __restrict__ inp, int N, int ntiles){
  __half* sW = smem;
  __half* sA = smem + GATES*SROW;
  __shared__ int s_tile;
  int tid = threadIdx.x;
  const uint4* gw = (const uint4*)g_Wih;
  for (int i = tid; i < GATES*D/8; i += NTHR){
    int col = i >> 4, kq = i & 15;
    *(uint4*)(sW + col*SROW + kq*8) = gw[i];
  }
  int lane = tid & 31, warp = tid >> 5, q = lane & 3;
  int nb = warp*32;
  for(;;){
    if (tid == 0) s_tile = atomicAdd(&g_tick[0], 1);
    __syncthreads();
    int blk = s_tile; if (blk >= ntiles) break;
    for (int i = tid; i < MT*D; i += NTHR){
      int r = i >> 7, k = i & 127;
      int gi = blk*MT + r;
      float v = (gi < N) ? inp[(size_t)gi*D + k] : 0.f;
      sA[r*SROW + k] = __float2half(v);
    }
    __syncthreads();
    float acc[4][4][4];
#pragma unroll
    for(int m=0;m<4;m++)
#pragma unroll
    for(int nt=0;nt<4;nt++){
      int col = nb + nt*8 + q*2;
      float b0 = g_bias[col], b1 = g_bias[col+1];
      acc[m][nt][0]=b0; acc[m][nt][1]=b1; acc[m][nt][2]=b0; acc[m][nt][3]=b1;
    }
#pragma unroll
    for(int kb=0;kb<8;kb++){
      unsigned a[4][4], b[4][2];
#pragma unroll
      for(int m=0;m<4;m++){
        unsigned ad = su(sA + (m*16 + (lane&15))*SROW + kb*16 + ((lane>>4)<<3));
        ldsm4(ad, a[m][0],a[m][1],a[m][2],a[m][3]);
      }
#pragma unroll
      for(int nt=0;nt<4;nt++){
        int r = lane & 15;
        unsigned bd = su(sW + (nb + nt*8 + (r&7))*SROW + kb*16 + ((r>>3)<<3));
        ldsm2(bd, b[nt][0], b[nt][1]);
      }
#pragma unroll
      for(int m=0;m<4;m++)
#pragma unroll
      for(int nt=0;nt<4;nt++)
        mmaf(acc[m][nt], a[m], b[nt][0], b[nt][1]);
    }
#pragma unroll
    for(int m=0;m<4;m++){
      int r0 = m*16 + (lane>>2);
#pragma unroll
      for(int nt=0;nt<4;nt++){
        int col = nb + nt*8 + q*2;
        int n0 = blk*MT + r0, n1 = n0 + 8;
        if (n0 < N) *(__half2*)&g_XWh[(size_t)n0*GATES + col] = __floats2half2_rn(acc[m][nt][0],acc[m][nt][1]);
        if (n1 < N) *(__half2*)&g_XWh[(size_t)n1*GATES + col] = __floats2half2_rn(acc[m][nt][2],acc[m][nt][3]);
      }
    }
    __syncthreads();   // sA reads done before next tile's fill
  }
}

// ---------------- recurrent LSTM: two independent 8-warp halves, double-buffered h ----------------
__global__ void __launch_bounds__(NTHR,1) k_lstm(const int* __restrict__ trg, int E, int N, int ngrp){
  __half* sW = smem;
  __half* sA = smem + GATES*SROW;          // 2 halves x 2 bufs x 32 rows x SROW
  __shared__ int s_tile[2];
  int tid = threadIdx.x;
  const uint4* gw = (const uint4*)g_Wrec;
  for (int i = tid; i < GATES*D/8; i += NTHR){
    int col = i >> 4, kq = i & 15;
    *(uint4*)(sW + col*SROW + kq*8) = gw[i];
  }
  __syncthreads();

  int half = tid >> 8;                     // 0 or 1
  int tid2 = tid & 255;
  int lane = tid & 31, warp8 = (tid >> 5) & 7, q = lane & 3;
  int nb = warp8 * 64;                     // 64 gate-cols per warp
  __half* hA = sA + half * (2*MG*SROW);    // this half's two buffers
  int bid = half + 1;                      // named barrier id

  for(;;){
    if (tid2 == 0) s_tile[half] = atomicAdd(&g_tick[1], 1);
    barh(bid);                             // ticket visible; prior h-store done
    int grp = s_tile[half]; if (grp >= ngrp) break;

    for (int i = tid2; i < 2*MG*SROW/8; i += 256) *(uint4*)(hA + i*8) = make_uint4(0,0,0,0);

    int s0[2], s1[2], d0[2], d1[2];
#pragma unroll
    for(int m=0;m<2;m++){
      int r = m*16 + (lane>>2);
      int i0 = grp*MG + r, i1 = i0 + 8;
      int n0 = g_perm[i0 < N ? i0 : N-1];
      int n1 = g_perm[i1 < N ? i1 : N-1];
      s0[m] = g_start[n0]; d0[m] = (i0<N) ? g_deg[n0] : 0;
      s1[m] = g_start[n1]; d1[m] = (i1<N) ? g_deg[n1] : 0;
    }
    int tmax = g_deg[g_perm[grp*MG]];      // sorted desc -> group max
    barh(bid);                             // zeros visible before first writes/reads

    float cc[2][8];
#pragma unroll
    for(int m=0;m<2;m++)
#pragma unroll
    for(int nt=0;nt<8;nt++) cc[m][nt]=0.f;

    // prefetch neighbor indices for t=0
    int pt0[2], pt1[2];
#pragma unroll
    for(int m=0;m<2;m++){
      pt0[m] = trg[s0[m] < E ? s0[m] : E-1];
      pt1[m] = trg[s1[m] < E ? s1[m] : E-1];
    }

    float acc[2][8][4];
    for(int t=0; t<tmax; t++){
      __half* bufPrev = hA + ((t+1)&1)*(MG*SROW);   // == (t-1)&1
      __half* bufCur  = hA + (t&1)*(MG*SROW);
      // gates init = XWh[trg] (bias folded in); issue gathers first to hide L2 latency
#pragma unroll
      for(int m=0;m<2;m++){
        const __half2* x0 = (const __half2*)&g_XWh[(size_t)pt0[m]*GATES];
        const __half2* x1 = (const __half2*)&g_XWh[(size_t)pt1[m]*GATES];
#pragma unroll
        for(int nt=0;nt<8;nt++){
          int ci = (nb + nt*8 + q*2) >> 1;
          float2 f0 = __half22float2(x0[ci]);
          float2 f1 = __half22float2(x1[ci]);
          acc[m][nt][0]=f0.x; acc[m][nt][1]=f0.y; acc[m][nt][2]=f1.x; acc[m][nt][3]=f1.y;
        }
      }
      // prefetch indices for t+1
#pragma unroll
      for(int m=0;m<2;m++){
        int e0 = s0[m]+t+1; if (e0 >= E) e0 = E-1;
        int e1 = s1[m]+t+1; if (e1 >= E) e1 = E-1;
        pt0[m] = trg[e0]; pt1[m] = trg[e1];
      }
      if (t > 0){
#pragma unroll
        for(int kb=0;kb<8;kb++){
          unsigned a[2][4], b[8][2];
#pragma unroll
          for(int m=0;m<2;m++){
            unsigned ad = su(bufPrev + (m*16 + (lane&15))*SROW + kb*16 + ((lane>>4)<<3));
            ldsm4(ad, a[m][0],a[m][1],a[m][2],a[m][3]);
          }
#pragma unroll
          for(int nt=0;nt<8;nt++){
            int r = lane & 15;
            unsigned bd = su(sW + (nb + nt*8 + (r&7))*SROW + kb*16 + ((r>>3)<<3));
            ldsm2(bd, b[nt][0], b[nt][1]);
          }
#pragma unroll
          for(int m=0;m<2;m++)
#pragma unroll
          for(int nt=0;nt<8;nt++)
            mmaf(acc[m][nt], a[m], b[nt][0], b[nt][1]);
        }
      }
      // NO mid barrier: cell update writes bufCur while other warps may still read bufPrev

      // cell update: pair-exchange gives each lane a full (i,f,g,o) quadruple
#pragma unroll
      for(int m=0;m<2;m++){
        int mydeg = (q&1) ? d1[m] : d0[m];
        bool act = t < mydeg;
        int row = m*16 + (lane>>2) + ((q&1)<<3);
#pragma unroll
        for(int nt=0;nt<8;nt++){
          float c0=acc[m][nt][0], c1=acc[m][nt][1], c2=acc[m][nt][2], c3=acc[m][nt][3];
          float v0 = (q&1)? c0 : c2;
          float v1 = (q&1)? c1 : c3;
          float w0 = __shfl_xor_sync(0xffffffffu, v0, 1);
          float w1 = __shfl_xor_sync(0xffffffffu, v1, 1);
          float gi = (q&1)? w0 : c0;
          float gf = (q&1)? w1 : c1;
          float gg = (q&1)? c2 : w0;
          float go = (q&1)? c3 : w1;
          int unit = (nb>>2) + nt*2 + (q>>1);
          int off = row*SROW + unit;
          if (act){
            float cn = fsig(gf)*cc[m][nt] + fsig(gi)*ftanh(gg);
            float hn = fsig(go)*ftanh(cn);
            cc[m][nt] = cn;
            bufCur[off] = __float2half(hn);
          } else {
            bufCur[off] = bufPrev[off];   // carry frozen h into current buffer
          }
        }
      }
      barh(bid);                           // h writes done before next step's ldmatrix
    }

    __half* bufLast = hA + (((tmax-1)&1))*(MG*SROW);   // tmax==0 -> buf1 (zeroed)
    for (int i = tid2; i < MG*D; i += 256){
      int r = i >> 7, k = i & 127;
      int gi = grp*MG + r;
      if (gi < N) g_Hh[(size_t)g_perm[gi]*D + k] = bufLast[r*SROW + k];
    }
  }
}

// ---------------- out = [x | h] @ W_out  (persistent, fp16 mma) ----------------
__global__ void __launch_bounds__(NTHR,1) k_out(const float* __restrict__ inp,
                                                float* __restrict__ out, int N, int ntiles){
  __half* sW = smem;              // 128 x OROW
  __half* sA = smem + D*OROW;     // 64 x OROW
  __shared__ int s_tile;
  int tid = threadIdx.x;
  const uint4* gw = (const uint4*)g_Wout;
  for (int i = tid; i < D*256/8; i += NTHR){
    int j = i >> 5, kq = i & 31;
    *(uint4*)(sW + j*OROW + kq*8) = gw[i];
  }
  int lane = tid & 31, warp = tid >> 5, q = lane & 3;
  int nbQ = warp*8;
  for(;;){
    if (tid == 0) s_tile = atomicAdd(&g_tick[2], 1);
    __syncthreads();
    int blk = s_tile; if (blk >= ntiles) break;
    for (int i = tid; i < MT*D; i += NTHR){
      int r = i >> 7, k = i & 127;
      int gi = blk*MT + r;
      float v = (gi < N) ? inp[(size_t)gi*D + k] : 0.f;
      sA[r*OROW + k] = __float2half(v);
      sA[r*OROW + 128 + k] = (gi < N) ? g_Hh[(size_t)gi*D + k] : __float2half(0.f);
    }
    __syncthreads();
    float acc[4][4];
#pragma unroll
    for(int m=0;m<4;m++){ acc[m][0]=0;acc[m][1]=0;acc[m][2]=0;acc[m][3]=0; }
#pragma unroll
    for(int kb=0;kb<16;kb++){
      unsigned a[4][4], b0, b1;
#pragma unroll
      for(int m=0;m<4;m++){
        unsigned ad = su(sA + (m*16 + (lane&15))*OROW + kb*16 + ((lane>>4)<<3));
        ldsm4(ad, a[m][0],a[m][1],a[m][2],a[m][3]);
      }
      {
        int r = lane & 15;
        unsigned bd = su(sW + (nbQ + (r&7))*OROW + kb*16 + ((r>>3)<<3));
        ldsm2(bd, b0, b1);
      }
#pragma unroll
      for(int m=0;m<4;m++)
        mmaf(acc[m], a[m], b0, b1);
    }
#pragma unroll
    for(int m=0;m<4;m++){
      int r0 = m*16 + (lane>>2);
      int col = nbQ + q*2;
      int n0 = blk*MT + r0, n1 = n0 + 8;
      if (n0 < N) *(float2*)&out[(size_t)n0*D + col] = make_float2(acc[m][0],acc[m][1]);
      if (n1 < N) *(float2*)&out[(size_t)n1*D + col] = make_float2(acc[m][2],acc[m][3]);
    }
    __syncthreads();   // sA reads done before next tile's fill
  }
}

extern "C" void kernel_launch(void* const* d_in, const int* in_sizes, int n_in,
                              void* d_out, int out_size){
  const float* inp  = (const float*)d_in[0];
  const float* Wih  = (const float*)d_in[1];
  const float* Whh  = (const float*)d_in[2];
  const float* bih  = (const float*)d_in[3];
  const float* bhh  = (const float*)d_in[4];
  const float* Wout = (const float*)d_in[5];
  const int*   src  = (const int*)d_in[6];
  const int*   trg  = (const int*)d_in[7];
  const int*   pmax = (n_in > 8) ? (const int*)d_in[8] : nullptr;

  int N = in_sizes[0] / D;
  int E = in_sizes[6];
  int NT = (N + MT - 1) / MT;
  int NG = (N + MG - 1) / MG;
  int smW = (GATES*SROW + MT*SROW) * (int)sizeof(__half);     // 156,672 B
  int smL = (GATES*SROW + 2*2*MG*SROW) * (int)sizeof(__half); // 174,080 B
  int smO = (D*OROW + MT*OROW) * (int)sizeof(__half);         // 101,376 B

  int dev = 0, sms = 148;
  cudaGetDevice(&dev);
  cudaDeviceGetAttribute(&sms, cudaDevAttrMultiProcessorCount, dev);
  int gridP = sms < NT ? sms : NT;

  cudaFuncSetAttribute(k_xw,   cudaFuncAttributeMaxDynamicSharedMemorySize, smW);
  cudaFuncSetAttribute(k_lstm, cudaFuncAttributeMaxDynamicSharedMemorySize, smL);
  cudaFuncSetAttribute(k_out,  cudaFuncAttributeMaxDynamicSharedMemorySize, smO);

  k_prep<<<(GATES*D + 255)/256, 256>>>(Wih, Whh, bih, bhh, Wout);
  k_startdeg<<<(N + 255)/256, 256>>>(src, E, N, pmax);
  k_scan<<<1, NBINS>>>();
  k_scatter<<<(N + 255)/256, 256>>>(N);
  k_xw  <<<gridP, NTHR, smW>>>(inp, N, NT);
  k_lstm<<<gridP, NTHR, smL>>>(trg, E, N, NG);
  k_out <<<gridP, NTHR, smO>>>(inp, (float*)d_out, N, NT);
}

// round 15
// speedup vs baseline: 1.7907x; 1.7907x over previous
#include <cuda_runtime.h>
#include <cuda_fp16.h>
#include <cstdint>

#define D 128
#define GATES 512
#define NMAX 30016
#define MT 64
#define MG 32            // nodes per half-group in k_lstm
#define SROW 136
#define OROW 264
#define NBINS 64
#define NTHR 512

__device__ __half g_XWh[(size_t)NMAX * GATES];   // fp16 x-transform, FRAGMENT order [w8][q][nt][j]
__device__ __half g_Hh[(size_t)NMAX * D];
__device__ __half g_Wrec[GATES * D];
__device__ __half g_Wih [GATES * D];
__device__ __half g_Wout[D * 256];
__device__ float  g_bias[GATES];
__device__ int g_start[NMAX], g_deg[NMAX], g_perm[NMAX];
__device__ int g_hist[NBINS], g_offs[NBINS];
__device__ int g_tick[4];

__device__ __forceinline__ unsigned su(const void* p){ return (unsigned)__cvta_generic_to_shared(p); }
__device__ __forceinline__ void ldsm4(unsigned a,unsigned&r0,unsigned&r1,unsigned&r2,unsigned&r3){
  asm volatile("ldmatrix.sync.aligned.m8n8.x4.shared.b16 {%0,%1,%2,%3},[%4];"
    :"=r"(r0),"=r"(r1),"=r"(r2),"=r"(r3):"r"(a));
}
__device__ __forceinline__ void ldsm2(unsigned a,unsigned&r0,unsigned&r1){
  asm volatile("ldmatrix.sync.aligned.m8n8.x2.shared.b16 {%0,%1},[%2];"
    :"=r"(r0),"=r"(r1):"r"(a));
}
__device__ __forceinline__ void mmaf(float* d,const unsigned* a,unsigned b0,unsigned b1){
  asm volatile("mma.sync.aligned.m16n8k16.row.col.f32.f16.f16.f32 {%0,%1,%2,%3},{%4,%5,%6,%7},{%8,%9},{%0,%1,%2,%3};"
    :"+f"(d[0]),"+f"(d[1]),"+f"(d[2]),"+f"(d[3])
    :"r"(a[0]),"r"(a[1]),"r"(a[2]),"r"(a[3]),"r"(b0),"r"(b1));
}
__device__ __forceinline__ float ftanh(float x){ float y; asm("tanh.approx.f32 %0,%1;":"=f"(y):"f"(x)); return y; }
__device__ __forceinline__ float fsig (float x){ return fmaf(0.5f, ftanh(0.5f*x), 0.5f); }
__device__ __forceinline__ void barh(int id){ asm volatile("bar.sync %0, 256;" :: "r"(id) : "memory"); }

// gate-col -> fragment position within a node's 512-gate row
__device__ __forceinline__ int fragpos(int col){
  return (col & 0x1C0) | (((col>>1)&3)<<4) | (((col>>3)&7)<<1) | (col&1);
}

// ---------------- prep: reorder/convert weights (col' = unit*4 + gate) + clear counters ----------------
__global__ void k_prep(const float* Wih, const float* Whh, const float* bih,
                       const float* bhh, const float* Wout){
  int idx = blockIdx.x*blockDim.x + threadIdx.x;
  if (blockIdx.x == 0){
    if (threadIdx.x < NBINS) g_hist[threadIdx.x] = 0;
    if (threadIdx.x < 4) g_tick[threadIdx.x] = 0;
  }
  if (idx < GATES*D){
    int col = idx >> 7, k = idx & 127;
    int u = col >> 2, gg = col & 3;
    int j = gg*D + u;
    g_Wrec[col*D + k] = __float2half(Whh[j*D + k]);
    g_Wih [col*D + k] = __float2half(Wih[j*D + k]);
    if (k == 0) g_bias[col] = bih[j] + bhh[j];
  }
  if (idx < D*256){
    int j = idx >> 8, k = idx & 255;
    g_Wout[idx] = __float2half(Wout[k*D + j]);
  }
}

// ---------------- CSR from sorted src + degree clamp + fused histogram ----------------
__global__ void k_startdeg(const int* src, int E, int N, const int* pmax){
  __shared__ int h[NBINS];
  if (threadIdx.x < NBINS) h[threadIdx.x] = 0;
  __syncthreads();
  int i = blockIdx.x*blockDim.x + threadIdx.x;
  if (i < N){
    int md = pmax ? *pmax : 48;
    int lo=0, hi=E; while(lo<hi){int m=(lo+hi)>>1; if(src[m]<i) lo=m+1; else hi=m;}
    int s=lo; lo=s; hi=E; while(lo<hi){int m=(lo+hi)>>1; if(src[m]<i+1) lo=m+1; else hi=m;}
    g_start[i]=s; int d=lo-s; d = d<md ? d : md; g_deg[i]=d;
    atomicAdd(&h[min(d,NBINS-1)],1);
  }
  __syncthreads();
  if (threadIdx.x < NBINS && h[threadIdx.x]) atomicAdd(&g_hist[threadIdx.x], h[threadIdx.x]);
}
// offs[d] = count of nodes with bin > d  (descending-degree layout)
__global__ void k_scan(){
  __shared__ int s[NBINS];
  int d = threadIdx.x;
  s[d] = g_hist[d];
  __syncthreads();
  int run = 0;
  for (int j = d+1; j < NBINS; j++) run += s[j];
  g_offs[d] = run;
}
__global__ void k_scatter(int N){
  __shared__ int cnt[NBINS], base[NBINS];
  if(threadIdx.x<NBINS) cnt[threadIdx.x]=0;
  __syncthreads();
  int i=blockIdx.x*blockDim.x+threadIdx.x;
  int b=0,r=0;
  if(i<N){ b=min(g_deg[i],NBINS-1); r=atomicAdd(&cnt[b],1); }
  __syncthreads();
  if(threadIdx.x<NBINS && cnt[threadIdx.x]) base[threadIdx.x]=atomicAdd(&g_offs[threadIdx.x],cnt[threadIdx.x]);
  __syncthreads();
  if(i<N) g_perm[base[b]+r]=i;
}

// ---------------- XW = input @ W_ih'^T + bias'  (persistent, fp16 mma, fragment-order store) ----------------
extern __shared__ __half smem[];
__global__ void __launch_bounds__(NTHR,1) k_xw(const float* __restrict__ inp, int N, int ntiles){
  __half* sW = smem;
  __half* sA = smem + GATES*SROW;
  __shared__ int s_tile;
  int tid = threadIdx.x;
  const uint4* gw = (const uint4*)g_Wih;
  for (int i = tid; i < GATES*D/8; i += NTHR){
    int col = i >> 4, kq = i & 15;
    *(uint4*)(sW + col*SROW + kq*8) = gw[i];
  }
  int lane = tid & 31, warp = tid >> 5, q = lane & 3;
  int nb = warp*32;
  for(;;){
    if (tid == 0) s_tile = atomicAdd(&g_tick[0], 1);
    __syncthreads();
    int blk = s_tile; if (blk >= ntiles) break;
    for (int i = tid; i < MT*D; i += NTHR){
      int r = i >> 7, k = i & 127;
      int gi = blk*MT + r;
      float v = (gi < N) ? inp[(size_t)gi*D + k] : 0.f;
      sA[r*SROW + k] = __float2half(v);
    }
    __syncthreads();
    float acc[4][4][4];
#pragma unroll
    for(int m=0;m<4;m++)
#pragma unroll
    for(int nt=0;nt<4;nt++){
      int col = nb + nt*8 + q*2;
      float b0 = g_bias[col], b1 = g_bias[col+1];
      acc[m][nt][0]=b0; acc[m][nt][1]=b1; acc[m][nt][2]=b0; acc[m][nt][3]=b1;
    }
#pragma unroll
    for(int kb=0;kb<8;kb++){
      unsigned a[4][4], b[4][2];
#pragma unroll
      for(int m=0;m<4;m++){
        unsigned ad = su(sA + (m*16 + (lane&15))*SROW + kb*16 + ((lane>>4)<<3));
        ldsm4(ad, a[m][0],a[m][1],a[m][2],a[m][3]);
      }
#pragma unroll
      for(int nt=0;nt<4;nt++){
        int r = lane & 15;
        unsigned bd = su(sW + (nb + nt*8 + (r&7))*SROW + kb*16 + ((r>>3)<<3));
        ldsm2(bd, b[nt][0], b[nt][1]);
      }
#pragma unroll
      for(int m=0;m<4;m++)
#pragma unroll
      for(int nt=0;nt<4;nt++)
        mmaf(acc[m][nt], a[m], b[nt][0], b[nt][1]);
    }
#pragma unroll
    for(int m=0;m<4;m++){
      int r0 = m*16 + (lane>>2);
#pragma unroll
      for(int nt=0;nt<4;nt++){
        int col = nb + nt*8 + q*2;
        int fr = fragpos(col);
        int n0 = blk*MT + r0, n1 = n0 + 8;
        if (n0 < N) *(__half2*)&g_XWh[(size_t)n0*GATES + fr] = __floats2half2_rn(acc[m][nt][0],acc[m][nt][1]);
        if (n1 < N) *(__half2*)&g_XWh[(size_t)n1*GATES + fr] = __floats2half2_rn(acc[m][nt][2],acc[m][nt][3]);
      }
    }
    __syncthreads();   // sA reads done before next tile's fill
  }
}

// ---------------- recurrent LSTM: two independent 8-warp halves, 32 nodes each ----------------
__global__ void __launch_bounds__(NTHR,1) k_lstm(const int* __restrict__ trg, int E, int N, int ngrp){
  __half* sW = smem;
  __half* sA = smem + GATES*SROW;          // 2 halves x 32 rows x SROW
  __shared__ int s_tile[2];
  int tid = threadIdx.x;
  const uint4* gw = (const uint4*)g_Wrec;
  for (int i = tid; i < GATES*D/8; i += NTHR){
    int col = i >> 4, kq = i & 15;
    *(uint4*)(sW + col*SROW + kq*8) = gw[i];
  }
  __syncthreads();

  int half = tid >> 8;                     // 0 or 1
  int tid2 = tid & 255;
  int lane = tid & 31, warp8 = (tid >> 5) & 7, q = lane & 3;
  int nb = warp8 * 64;                     // 64 gate-cols per warp
  int fbase = warp8*8 + q*2;               // uint4 index of this lane's fragment block
  __half* hA = sA + half * MG * SROW;
  int bid = half + 1;                      // named barrier id

  for(;;){
    if (tid2 == 0) s_tile[half] = atomicAdd(&g_tick[1], 1);
    barh(bid);                             // ticket visible; prior h-store done
    int grp = s_tile[half]; if (grp >= ngrp) break;

    for (int i = tid2; i < MG*SROW/8; i += 256) *(uint4*)(hA + i*8) = make_uint4(0,0,0,0);

    int s0[2], s1[2], d0[2], d1[2];
#pragma unroll
    for(int m=0;m<2;m++){
      int r = m*16 + (lane>>2);
      int i0 = grp*MG + r, i1 = i0 + 8;
      int n0 = g_perm[i0 < N ? i0 : N-1];
      int n1 = g_perm[i1 < N ? i1 : N-1];
      s0[m] = g_start[n0]; d0[m] = (i0<N) ? g_deg[n0] : 0;
      s1[m] = g_start[n1]; d1[m] = (i1<N) ? g_deg[n1] : 0;
    }
    int tmax = g_deg[g_perm[grp*MG]];      // sorted desc -> group max
    barh(bid);                             // zeros visible before first writes/reads

    float cc[2][8];
#pragma unroll
    for(int m=0;m<2;m++)
#pragma unroll
    for(int nt=0;nt<8;nt++) cc[m][nt]=0.f;

    // prefetch neighbor indices for t=0
    int pt0[2], pt1[2];
#pragma unroll
    for(int m=0;m<2;m++){
      pt0[m] = trg[s0[m] < E ? s0[m] : E-1];
      pt1[m] = trg[s1[m] < E ? s1[m] : E-1];
    }

    float acc[2][8][4];
    for(int t=0; t<tmax; t++){
      // gates init = XWh[trg] in fragment order: 4 x uint4 coalesced loads per lane
#pragma unroll
      for(int m=0;m<2;m++){
        const uint4* x0 = (const uint4*)(g_XWh + (size_t)pt0[m]*GATES) + fbase;
        const uint4* x1 = (const uint4*)(g_XWh + (size_t)pt1[m]*GATES) + fbase;
        uint4 u0a = x0[0], u0b = x0[1];
        uint4 u1a = x1[0], u1b = x1[1];
        const __half2* h0a = (const __half2*)&u0a;
        const __half2* h0b = (const __half2*)&u0b;
        const __half2* h1a = (const __half2*)&u1a;
        const __half2* h1b = (const __half2*)&u1b;
#pragma unroll
        for(int nt=0;nt<4;nt++){
          float2 f0 = __half22float2(h0a[nt]);
          float2 f1 = __half22float2(h1a[nt]);
          acc[m][nt][0]=f0.x; acc[m][nt][1]=f0.y; acc[m][nt][2]=f1.x; acc[m][nt][3]=f1.y;
          float2 g0 = __half22float2(h0b[nt]);
          float2 g1 = __half22float2(h1b[nt]);
          acc[m][nt+4][0]=g0.x; acc[m][nt+4][1]=g0.y; acc[m][nt+4][2]=g1.x; acc[m][nt+4][3]=g1.y;
        }
      }
      // prefetch indices for t+1
#pragma unroll
      for(int m=0;m<2;m++){
        int e0 = s0[m]+t+1; if (e0 >= E) e0 = E-1;
        int e1 = s1[m]+t+1; if (e1 >= E) e1 = E-1;
        pt0[m] = trg[e0]; pt1[m] = trg[e1];
      }
      if (t > 0){
#pragma unroll
        for(int kb=0;kb<8;kb++){
          unsigned a[2][4], b[8][2];
#pragma unroll
          for(int m=0;m<2;m++){
            unsigned ad = su(hA + (m*16 + (lane&15))*SROW + kb*16 + ((lane>>4)<<3));
            ldsm4(ad, a[m][0],a[m][1],a[m][2],a[m][3]);
          }
#pragma unroll
          for(int nt=0;nt<8;nt++){
            int r = lane & 15;
            unsigned bd = su(sW + (nb + nt*8 + (r&7))*SROW + kb*16 + ((r>>3)<<3));
            ldsm2(bd, b[nt][0], b[nt][1]);
          }
#pragma unroll
          for(int m=0;m<2;m++)
#pragma unroll
          for(int nt=0;nt<8;nt++)
            mmaf(acc[m][nt], a[m], b[nt][0], b[nt][1]);
        }
      }
      barh(bid);                           // hA reads done before h writes

      // cell update: pair-exchange gives each lane a full (i,f,g,o) quadruple
#pragma unroll
      for(int m=0;m<2;m++){
        int mydeg = (q&1) ? d1[m] : d0[m];
        bool act = t < mydeg;
        int row = m*16 + (lane>>2) + ((q&1)<<3);
#pragma unroll
        for(int nt=0;nt<8;nt++){
          float c0=acc[m][nt][0], c1=acc[m][nt][1], c2=acc[m][nt][2], c3=acc[m][nt][3];
          float v0 = (q&1)? c0 : c2;
          float v1 = (q&1)? c1 : c3;
          float w0 = __shfl_xor_sync(0xffffffffu, v0, 1);
          float w1 = __shfl_xor_sync(0xffffffffu, v1, 1);
          float gi = (q&1)? w0 : c0;
          float gf = (q&1)? w1 : c1;
          float gg = (q&1)? c2 : w0;
          float go = (q&1)? c3 : w1;
          float cn = fsig(gf)*cc[m][nt] + fsig(gi)*ftanh(gg);
          float hn = fsig(go)*ftanh(cn);
          if (act){
            cc[m][nt] = cn;
            int unit = (nb>>2) + nt*2 + (q>>1);
            hA[row*SROW + unit] = __float2half(hn);
          }
        }
      }
      barh(bid);                           // h writes done before next step's ldmatrix
    }

    for (int i = tid2; i < MG*D; i += 256){
      int r = i >> 7, k = i & 127;
      int gi = grp*MG + r;
      if (gi < N) g_Hh[(size_t)g_perm[gi]*D + k] = hA[r*SROW + k];
    }
  }
}

// ---------------- out = [x | h] @ W_out  (persistent, fp16 mma) ----------------
__global__ void __launch_bounds__(NTHR,1) k_out(const float* __restrict__ inp,
                                                float* __restrict__ out, int N, int ntiles){
  __half* sW = smem;              // 128 x OROW
  __half* sA = smem + D*OROW;     // 64 x OROW
  __shared__ int s_tile;
  int tid = threadIdx.x;
  const uint4* gw = (const uint4*)g_Wout;
  for (int i = tid; i < D*256/8; i += NTHR){
    int j = i >> 5, kq = i & 31;
    *(uint4*)(sW + j*OROW + kq*8) = gw[i];
  }
  int lane = tid & 31, warp = tid >> 5, q = lane & 3;
  int nbQ = warp*8;
  for(;;){
    if (tid == 0) s_tile = atomicAdd(&g_tick[2], 1);
    __syncthreads();
    int blk = s_tile; if (blk >= ntiles) break;
    for (int i = tid; i < MT*D; i += NTHR){
      int r = i >> 7, k = i & 127;
      int gi = blk*MT + r;
      float v = (gi < N) ? inp[(size_t)gi*D + k] : 0.f;
      sA[r*OROW + k] = __float2half(v);
      sA[r*OROW + 128 + k] = (gi < N) ? g_Hh[(size_t)gi*D + k] : __float2half(0.f);
    }
    __syncthreads();
    float acc[4][4];
#pragma unroll
    for(int m=0;m<4;m++){ acc[m][0]=0;acc[m][1]=0;acc[m][2]=0;acc[m][3]=0; }
#pragma unroll
    for(int kb=0;kb<16;kb++){
      unsigned a[4][4], b0, b1;
#pragma unroll
      for(int m=0;m<4;m++){
        unsigned ad = su(sA + (m*16 + (lane&15))*OROW + kb*16 + ((lane>>4)<<3));
        ldsm4(ad, a[m][0],a[m][1],a[m][2],a[m][3]);
      }
      {
        int r = lane & 15;
        unsigned bd = su(sW + (nbQ + (r&7))*OROW + kb*16 + ((r>>3)<<3));
        ldsm2(bd, b0, b1);
      }
#pragma unroll
      for(int m=0;m<4;m++)
        mmaf(acc[m], a[m], b0, b1);
    }
#pragma unroll
    for(int m=0;m<4;m++){
      int r0 = m*16 + (lane>>2);
      int col = nbQ + q*2;
      int n0 = blk*MT + r0, n1 = n0 + 8;
      if (n0 < N) *(float2*)&out[(size_t)n0*D + col] = make_float2(acc[m][0],acc[m][1]);
      if (n1 < N) *(float2*)&out[(size_t)n1*D + col] = make_float2(acc[m][2],acc[m][3]);
    }
    __syncthreads();   // sA reads done before next tile's fill
  }
}

extern "C" void kernel_launch(void* const* d_in, const int* in_sizes, int n_in,
                              void* d_out, int out_size){
  const float* inp  = (const float*)d_in[0];
  const float* Wih  = (const float*)d_in[1];
  const float* Whh  = (const float*)d_in[2];
  const float* bih  = (const float*)d_in[3];
  const float* bhh  = (const float*)d_in[4];
  const float* Wout = (const float*)d_in[5];
  const int*   src  = (const int*)d_in[6];
  const int*   trg  = (const int*)d_in[7];
  const int*   pmax = (n_in > 8) ? (const int*)d_in[8] : nullptr;

  int N = in_sizes[0] / D;
  int E = in_sizes[6];
  int NT = (N + MT - 1) / MT;
  int NG = (N + MG - 1) / MG;
  int smW = (GATES*SROW + MT*SROW) * (int)sizeof(__half);   // 156,672 B
  int smO = (D*OROW + MT*OROW) * (int)sizeof(__half);       // 101,376 B

  int dev = 0, sms = 148;
  cudaGetDevice(&dev);
  cudaDeviceGetAttribute(&sms, cudaDevAttrMultiProcessorCount, dev);
  int gridP = sms < NT ? sms : NT;

  cudaFuncSetAttribute(k_xw,   cudaFuncAttributeMaxDynamicSharedMemorySize, smW);
  cudaFuncSetAttribute(k_lstm, cudaFuncAttributeMaxDynamicSharedMemorySize, smW);
  cudaFuncSetAttribute(k_out,  cudaFuncAttributeMaxDynamicSharedMemorySize, smO);

  k_prep<<<(GATES*D + 255)/256, 256>>>(Wih, Whh, bih, bhh, Wout);
  k_startdeg<<<(N + 255)/256, 256>>>(src, E, N, pmax);
  k_scan<<<1, NBINS>>>();
  k_scatter<<<(N + 255)/256, 256>>>(N);
  k_xw  <<<gridP, NTHR, smW>>>(inp, N, NT);
  k_lstm<<<gridP, NTHR, smW>>>(trg, E, N, NG);
  k_out <<<gridP, NTHR, smO>>>(inp, (float*)d_out, N, NT);
}